// round 10
// baseline (speedup 1.0000x reference)
#include <cuda_runtime.h>
#include <math.h>

// SphereConv: out[2,B,F,L,M] from x[B,1,C,L,M] (complex as 2 arrays) and
// w[F,C,N,1] (complex), weights interp N=64->L=256, channel-mean, sqrt(1+l)
// scale, relu on real part.
//
// R9: all parallelism knobs were flat; only cache-policy moved the needle ->
// binder is DRAM-side efficiency. Old layout read 1KB fragments at 256KB
// strides. New layout: one block = 8 consecutive l's (512 threads), so each
// c-iteration reads 8KB contiguous per component -> 8x larger DRAM bursts,
// same minimal byte count. Keep evict_last x loads + streaming stores.
namespace {

constexpr int B = 4, C = 32, L = 256, M = 256, F = 8, N = 64;
constexpr int TL = 8;                  // l's per block
constexpr int THREADS = 64 * TL;       // 512
constexpr int CSTRIDE4 = L * M / 4;    // float4 stride between channels

__device__ __forceinline__ unsigned long long mk_persist_policy()
{
    unsigned long long pol;
    asm("createpolicy.fractional.L2::evict_last.b64 %0, 1.0;" : "=l"(pol));
    return pol;
}

__device__ __forceinline__ float4 ldg_persist(const float4* p,
                                              unsigned long long pol)
{
    float4 v;
    asm("ld.global.nc.L2::cache_hint.v4.f32 {%0,%1,%2,%3}, [%4], %5;"
        : "=f"(v.x), "=f"(v.y), "=f"(v.z), "=f"(v.w)
        : "l"(p), "l"(pol));
    return v;
}

__device__ __forceinline__ void stg_stream(float4* p, float4 v)
{
    asm volatile("st.global.cs.v4.f32 [%0], {%1,%2,%3,%4};"
                 :: "l"(p), "f"(v.x), "f"(v.y), "f"(v.z), "f"(v.w)
                 : "memory");
}

__device__ __forceinline__ void cplx_fma(float4& arf, float4& aif,
                                         float a, float bb,
                                         const float4& vr, const float4& vi)
{
    arf.x = fmaf(a, vr.x, fmaf(-bb, vi.x, arf.x));
    arf.y = fmaf(a, vr.y, fmaf(-bb, vi.y, arf.y));
    arf.z = fmaf(a, vr.z, fmaf(-bb, vi.z, arf.z));
    arf.w = fmaf(a, vr.w, fmaf(-bb, vi.w, arf.w));
    aif.x = fmaf(a, vi.x, fmaf( bb, vr.x, aif.x));
    aif.y = fmaf(a, vi.y, fmaf( bb, vr.y, aif.y));
    aif.z = fmaf(a, vi.z, fmaf( bb, vr.z, aif.z));
    aif.w = fmaf(a, vi.w, fmaf( bb, vr.w, aif.w));
}

__global__ __launch_bounds__(THREADS, 1)
void sphere_conv_kernel(const float* __restrict__ xr,
                        const float* __restrict__ xi,
                        const float* __restrict__ wr,
                        const float* __restrict__ wi,
                        float* __restrict__ out)
{
    const int bx    = blockIdx.x;
    const int b     = bx >> 5;            // bx / (L/TL)
    const int l0    = (bx & 31) * TL;     // first l of this tile

    // Interpolated weights: [lt][c][f], f fastest (8 floats -> 2 float4).
    __shared__ float swr[TL][C * F];
    __shared__ float swi[TL][C * F];

    const int tid = threadIdx.x;
    const int lt  = tid >> 6;             // which l within the tile
    const int m4  = tid & 63;             // float4 index within the M row
    const int l   = l0 + lt;

    // fill weights: TL*C*F = 2048 entries, 4 per thread
    for (int i = tid; i < TL * C * F; i += THREADS) {
        int wlt = i >> 8;                 // i / (C*F)
        int rem = i & 255;
        int c   = rem >> 3;               // rem / F
        int f   = rem & 7;
        int wl  = l0 + wlt;
        float t  = ((float)wl / (float)(L - 1)) * (float)(N - 1);
        int   lo = (int)floorf(t);
        lo = lo < 0 ? 0 : (lo > N - 2 ? N - 2 : lo);
        float frac = t - (float)lo;
        float sc = sqrtf(1.0f + (float)wl) * (1.0f / (float)C);
        int widx = (f * C + c) * N + lo;
        swr[wlt][rem] = (wr[widx] * (1.0f - frac) + wr[widx + 1] * frac) * sc;
        swi[wlt][rem] = (wi[widx] * (1.0f - frac) + wi[widx + 1] * frac) * sc;
    }
    __syncthreads();

    const unsigned long long pol = mk_persist_policy();

    const size_t base4 = ((size_t)b * C * L + l) * (M / 4) + m4;
    const float4* xr4 = reinterpret_cast<const float4*>(xr) + base4;
    const float4* xi4 = reinterpret_cast<const float4*>(xi) + base4;

    float4 ar[F], ai[F];
#pragma unroll
    for (int f = 0; f < F; ++f) {
        ar[f] = make_float4(0.f, 0.f, 0.f, 0.f);
        ai[f] = make_float4(0.f, 0.f, 0.f, 0.f);
    }

    const float4* swr4 = reinterpret_cast<const float4*>(swr[lt]);
    const float4* swi4 = reinterpret_cast<const float4*>(swi[lt]);

    // single-channel software prefetch
    float4 vr = ldg_persist(xr4, pol);
    float4 vi = ldg_persist(xi4, pol);

#pragma unroll 4
    for (int c = 0; c < C; ++c) {
        float4 nr, ni;
        if (c + 1 < C) {
            nr = ldg_persist(xr4 + (c + 1) * CSTRIDE4, pol);
            ni = ldg_persist(xi4 + (c + 1) * CSTRIDE4, pol);
        }
        float4 w0 = swr4[c * 2 + 0];
        float4 w1 = swr4[c * 2 + 1];
        float4 u0 = swi4[c * 2 + 0];
        float4 u1 = swi4[c * 2 + 1];
        float wv[8] = {w0.x, w0.y, w0.z, w0.w, w1.x, w1.y, w1.z, w1.w};
        float uv[8] = {u0.x, u0.y, u0.z, u0.w, u1.x, u1.y, u1.z, u1.w};
#pragma unroll
        for (int f = 0; f < F; ++f)
            cplx_fma(ar[f], ai[f], wv[f], uv[f], vr, vi);
        if (c + 1 < C) { vr = nr; vi = ni; }
    }

    // out shape (2, B, F, L, M); relu on real part; streaming stores.
    float4* out4 = reinterpret_cast<float4*>(out);
#pragma unroll
    for (int f = 0; f < F; ++f) {
        float4 r = ar[f];
        r.x = fmaxf(r.x, 0.f);
        r.y = fmaxf(r.y, 0.f);
        r.z = fmaxf(r.z, 0.f);
        r.w = fmaxf(r.w, 0.f);
        size_t or4 = (((size_t)(0 * B + b) * F + f) * L + l) * (M / 4) + m4;
        size_t oi4 = (((size_t)(1 * B + b) * F + f) * L + l) * (M / 4) + m4;
        stg_stream(out4 + or4, r);
        stg_stream(out4 + oi4, ai[f]);
    }
}

}  // namespace

extern "C" void kernel_launch(void* const* d_in, const int* in_sizes, int n_in,
                              void* d_out, int out_size)
{
    const float* xr = (const float*)d_in[0];
    const float* xi = (const float*)d_in[1];
    const float* wr = (const float*)d_in[2];
    const float* wi = (const float*)d_in[3];
    float* out = (float*)d_out;
    sphere_conv_kernel<<<(B * L) / TL, THREADS>>>(xr, xi, wr, wi, out);
}